// round 1
// baseline (speedup 1.0000x reference)
#include <cuda_runtime.h>
#include <math.h>

// Problem constants
#define B_SZ   4
#define T_SZ   16
#define C_SZ   3
#define H_SZ   256
#define W_SZ   256
#define N_PTS  8192
#define PATCH  9
#define EMBED  768
#define PDIM   243          // 9*9*3
#define KPAD   256          // padded K for X
#define M_ROWS 32768        // B*N

// Scratch (allocation-free rule: __device__ globals)
__device__ float g_X[(size_t)M_ROWS * KPAD];    // ~33.5 MB
__device__ float g_H[(size_t)M_ROWS * EMBED];   // ~96 MB

// ---------------------------------------------------------------------------
// Kernel 1: gather patches into g_X (row-major [M_ROWS][KPAD], cols 243..255 = 0)
// One block per patch (row), 256 threads, thread = column.
// ---------------------------------------------------------------------------
__global__ __launch_bounds__(256) void gather_kernel(
    const float* __restrict__ frames,
    const float* __restrict__ coords,
    const int*   __restrict__ t_src)
{
    int row = blockIdx.x;            // 0..32767
    int col = threadIdx.x;           // 0..255
    int b = row >> 13;               // /8192
    int n = row & (N_PTS - 1);

    float val = 0.0f;
    if (col < PDIM) {
        int c  = col % 3;
        int p  = col / 3;
        int dx = p % PATCH;
        int dy = p / PATCH;

        float cu = coords[(size_t)(b * N_PTS + n) * 2 + 0];
        float cv = coords[(size_t)(b * N_PTS + n) * 2 + 1];
        int u = (int)(cu * (float)(W_SZ - 1));   // trunc == floor (coords >= 0)
        int v = (int)(cv * (float)(H_SZ - 1));
        int t = t_src[b * N_PTS + n];

        int y = v + dy - (PATCH / 2);
        int x = u + dx - (PATCH / 2);
        y = min(max(y, 0), H_SZ - 1);
        x = min(max(x, 0), W_SZ - 1);

        size_t fidx = ((((size_t)b * T_SZ + t) * C_SZ + c) * H_SZ + y) * W_SZ + x;
        val = frames[fidx];
    }
    g_X[(size_t)row * KPAD + col] = val;
}

// ---------------------------------------------------------------------------
// Kernel 2/3: tiled fp32 GEMM  C[M][N] = act(A[M][lda(pad K)] * Bw[K][N] + bias)
// BM=128, BN=64, BK=16, 256 threads, each thread computes 8x4.
// A-side loads are UNGUARDED: requires ceil(K/16)*16 <= lda with zero padding
// (true for g_X: lda=256 pad-zeroed; and for H: K=768=lda).
// ---------------------------------------------------------------------------
template<bool GELU>
__global__ __launch_bounds__(256) void gemm_bias(
    const float* __restrict__ A,
    const float* __restrict__ Bw,
    const float* __restrict__ bias,
    float* __restrict__ C,
    int K, int lda, int N)
{
    __shared__ float As[16][128];   // transposed tile: As[k][row]
    __shared__ float Bs[16][64];

    const int bm0 = blockIdx.y * 128;
    const int bn0 = blockIdx.x * 64;
    const int t   = threadIdx.x;
    const int tx  = t & 15;         // col group: 16 * 4 = 64 cols
    const int ty  = t >> 4;         // row group: 16 * 8 = 128 rows

    float acc[8][4];
    #pragma unroll
    for (int i = 0; i < 8; i++)
        #pragma unroll
        for (int j = 0; j < 4; j++) acc[i][j] = 0.0f;

    const int ktiles = (K + 15) >> 4;

    for (int kt = 0; kt < ktiles; kt++) {
        const int k0 = kt << 4;

        // Load A tile: 128x16 = 512 float4, 2 per thread, coalesced-ish.
        #pragma unroll
        for (int l = 0; l < 2; l++) {
            int li  = t + 256 * l;          // 0..511
            int row = li >> 2;              // 0..127
            int kq  = (li & 3) << 2;        // 0,4,8,12
            float4 v = *(const float4*)(A + (size_t)(bm0 + row) * lda + k0 + kq);
            As[kq + 0][row] = v.x;
            As[kq + 1][row] = v.y;
            As[kq + 2][row] = v.z;
            As[kq + 3][row] = v.w;
        }
        // Load B tile: 16x64 = 256 float4, 1 per thread. Guard k (weights end at K).
        {
            int k  = t >> 4;                // 0..15
            int nq = (t & 15) << 2;         // 0..60
            float4 v = make_float4(0.f, 0.f, 0.f, 0.f);
            if (k0 + k < K)
                v = *(const float4*)(Bw + (size_t)(k0 + k) * N + bn0 + nq);
            *(float4*)&Bs[k][nq] = v;
        }
        __syncthreads();

        #pragma unroll
        for (int k = 0; k < 16; k++) {
            float4 a0 = *(const float4*)&As[k][ty * 8];
            float4 a1 = *(const float4*)&As[k][ty * 8 + 4];
            float4 bv = *(const float4*)&Bs[k][tx * 4];
            float a[8] = {a0.x, a0.y, a0.z, a0.w, a1.x, a1.y, a1.z, a1.w};
            float bb[4] = {bv.x, bv.y, bv.z, bv.w};
            #pragma unroll
            for (int i = 0; i < 8; i++)
                #pragma unroll
                for (int j = 0; j < 4; j++)
                    acc[i][j] += a[i] * bb[j];
        }
        __syncthreads();
    }

    // Epilogue: bias (+ exact GELU), float4 stores.
    const int col = bn0 + tx * 4;
    const float4 bb = *(const float4*)&bias[col];
    #pragma unroll
    for (int i = 0; i < 8; i++) {
        float4 v;
        v.x = acc[i][0] + bb.x;
        v.y = acc[i][1] + bb.y;
        v.z = acc[i][2] + bb.z;
        v.w = acc[i][3] + bb.w;
        if (GELU) {
            v.x = 0.5f * v.x * (1.0f + erff(v.x * 0.70710678118654752f));
            v.y = 0.5f * v.y * (1.0f + erff(v.y * 0.70710678118654752f));
            v.z = 0.5f * v.z * (1.0f + erff(v.z * 0.70710678118654752f));
            v.w = 0.5f * v.w * (1.0f + erff(v.w * 0.70710678118654752f));
        }
        *(float4*)(C + (size_t)(bm0 + ty * 8 + i) * N + col) = v;
    }
}

// ---------------------------------------------------------------------------
extern "C" void kernel_launch(void* const* d_in, const int* in_sizes, int n_in,
                              void* d_out, int out_size)
{
    const float* frames = (const float*)d_in[0];
    const float* coords = (const float*)d_in[1];
    const int*   t_src  = (const int*)  d_in[2];
    const float* W1     = (const float*)d_in[3];
    const float* b1     = (const float*)d_in[4];
    const float* W2     = (const float*)d_in[5];
    const float* b2     = (const float*)d_in[6];
    float*       out    = (float*)d_out;

    float *X, *H;
    cudaGetSymbolAddress((void**)&X, g_X);   // pure host query, capture-safe
    cudaGetSymbolAddress((void**)&H, g_H);

    // 1) gather
    gather_kernel<<<M_ROWS, 256>>>(frames, coords, t_src);

    // 2) H = gelu(X @ W1 + b1)   (M=32768, K=243 (pad 256), N=768)
    dim3 grid(EMBED / 64, M_ROWS / 128);
    gemm_bias<true><<<grid, 256>>>(X, W1, b1, H, PDIM, KPAD, EMBED);

    // 3) out = H @ W2 + b2       (K=768, lda=768)
    gemm_bias<false><<<grid, 256>>>(H, W2, b2, out, EMBED, EMBED, EMBED);
}

// round 3
// speedup vs baseline: 3.3393x; 3.3393x over previous
#include <cuda_runtime.h>
#include <math.h>
#include <stdint.h>

// Problem constants
#define B_SZ   4
#define T_SZ   16
#define C_SZ   3
#define H_SZ   256
#define W_SZ   256
#define N_PTS  8192
#define PATCH  9
#define EMBED  768
#define PDIM   243
#define KPAD   256
#define M_ROWS 32768

// Scratch (__device__ globals: allocation-free rule)
__device__ float g_X[(size_t)M_ROWS * KPAD];     // gathered patches, tf32-rounded, K-padded
__device__ float g_H[(size_t)M_ROWS * EMBED];    // hidden, tf32-rounded
__device__ float g_W1R[(size_t)KPAD * EMBED];    // W1 tf32-rounded, K-padded rows
__device__ float g_W2R[(size_t)EMBED * EMBED];   // W2 tf32-rounded

__device__ __forceinline__ float to_tf32(float x) {
    float y; asm("cvt.rna.tf32.f32 %0, %1;" : "=f"(y) : "f"(x)); return y;
}
__device__ __forceinline__ uint32_t smem_u32(const void* p) {
    uint32_t a;
    asm("{ .reg .u64 t; cvta.to.shared.u64 t, %1; cvt.u32.u64 %0, t; }" : "=r"(a) : "l"(p));
    return a;
}
__device__ __forceinline__ void cp16(uint32_t dst, const void* src) {
    asm volatile("cp.async.cg.shared.global [%0], [%1], 16;" :: "r"(dst), "l"(src));
}
#define CP_COMMIT() asm volatile("cp.async.commit_group;" ::: "memory")
#define CP_WAIT0()  asm volatile("cp.async.wait_group 0;" ::: "memory")

__device__ __forceinline__ void mma_tf32(float* c, const uint32_t* a, const uint32_t* b) {
    asm volatile(
        "mma.sync.aligned.m16n8k8.row.col.f32.tf32.tf32.f32 "
        "{%0,%1,%2,%3}, {%4,%5,%6,%7}, {%8,%9}, {%0,%1,%2,%3};"
        : "+f"(c[0]), "+f"(c[1]), "+f"(c[2]), "+f"(c[3])
        : "r"(a[0]), "r"(a[1]), "r"(a[2]), "r"(a[3]), "r"(b[0]), "r"(b[1]));
}

// ---------------------------------------------------------------------------
// Gather patches -> g_X (tf32-rounded, cols 243..255 zero)
// ---------------------------------------------------------------------------
__global__ __launch_bounds__(256) void gather_kernel(
    const float* __restrict__ frames,
    const float* __restrict__ coords,
    const int*   __restrict__ t_src)
{
    int row = blockIdx.x;
    int col = threadIdx.x;
    int b = row >> 13;
    int n = row & (N_PTS - 1);

    float val = 0.0f;
    if (col < PDIM) {
        int c  = col % 3;
        int p  = col / 3;
        int dx = p % PATCH;
        int dy = p / PATCH;
        float cu = coords[(size_t)(b * N_PTS + n) * 2 + 0];
        float cv = coords[(size_t)(b * N_PTS + n) * 2 + 1];
        int u = (int)(cu * (float)(W_SZ - 1));
        int v = (int)(cv * (float)(H_SZ - 1));
        int t = t_src[b * N_PTS + n];
        int y = min(max(v + dy - PATCH / 2, 0), H_SZ - 1);
        int x = min(max(u + dx - PATCH / 2, 0), W_SZ - 1);
        val = to_tf32(frames[((((size_t)b * T_SZ + t) * C_SZ + c) * H_SZ + y) * W_SZ + x]);
    }
    g_X[(size_t)row * KPAD + col] = val;
}

// ---------------------------------------------------------------------------
// Weight rounding (tf32) + K-pad for W1
// ---------------------------------------------------------------------------
__global__ __launch_bounds__(256) void round_w1(const float* __restrict__ W1) {
    int idx = blockIdx.x * 256 + threadIdx.x;        // over KPAD*EMBED
    if (idx >= KPAD * EMBED) return;
    int k = idx / EMBED;
    g_W1R[idx] = (k < PDIM) ? to_tf32(W1[idx - (k - k) * 0 + 0 * 0 + (size_t)k * EMBED + (idx % EMBED) - (size_t)k * EMBED + (size_t)k * EMBED - (size_t)k * EMBED + (size_t)k * EMBED + (idx % EMBED) - (idx % EMBED)]) : 0.0f;
}
// (clean version below actually used)
__global__ __launch_bounds__(256) void round_w1_clean(const float* __restrict__ W1) {
    int idx = blockIdx.x * 256 + threadIdx.x;
    if (idx >= KPAD * EMBED) return;
    int k = idx / EMBED;
    int n = idx % EMBED;
    g_W1R[idx] = (k < PDIM) ? to_tf32(W1[(size_t)k * EMBED + n]) : 0.0f;
}
__global__ __launch_bounds__(256) void round_w2(const float* __restrict__ W2) {
    int idx = blockIdx.x * 256 + threadIdx.x;
    if (idx < EMBED * EMBED) g_W2R[idx] = to_tf32(W2[idx]);
}

// ---------------------------------------------------------------------------
// TF32 mma.sync GEMM: C[M][768] = act(A[M][lda] * Bw[K][768] + bias)
// BM=128 BN=128 BK=32, 256 thr (2Mx4N warps, warp tile 64x32), double-buffered.
// A strides: smem 44 floats/row (conflict-free frags, 16B-aligned rows).
// B strides: smem 136 floats/row.
// ---------------------------------------------------------------------------
#define A_STRIDE 44
#define B_STRIDE 136
#define A_BYTES  (128 * A_STRIDE * 4)    // 22528
#define B_BYTES  (32 * B_STRIDE * 4)     // 17408
#define S_TOTAL  (2 * A_BYTES + 2 * B_BYTES)   // 79872

__device__ __forceinline__ void load_tiles(uint32_t sA, uint32_t sB,
                                           const float* __restrict__ Agm,
                                           const float* __restrict__ Bgm,
                                           int lda, int t)
{
    #pragma unroll
    for (int i = 0; i < 4; i++) {               // A: 128 rows x 8 float4
        int li = t + 256 * i;
        int row = li >> 3, q = li & 7;
        cp16(sA + row * (A_STRIDE * 4) + q * 16, Agm + (size_t)row * lda + q * 4);
    }
    #pragma unroll
    for (int i = 0; i < 4; i++) {               // B: 32 rows x 32 float4
        int li = t + 256 * i;
        int row = li >> 5, q = li & 31;
        cp16(sB + row * (B_STRIDE * 4) + q * 16, Bgm + (size_t)row * EMBED + q * 4);
    }
}

template<bool GELU, bool ROUND_OUT>
__global__ void __launch_bounds__(256, 2) gemm_mma(
    const float* __restrict__ A,
    const float* __restrict__ Bw,
    const float* __restrict__ bias,
    float* __restrict__ C,
    int KT, int lda)
{
    extern __shared__ char smem[];
    const uint32_t sb = smem_u32(smem);
    const uint32_t sA[2] = { sb, sb + A_BYTES };
    const uint32_t sB[2] = { sb + 2 * A_BYTES, sb + 2 * A_BYTES + B_BYTES };

    const int t    = threadIdx.x;
    const int w    = t >> 5;
    const int lane = t & 31;
    const int g    = lane >> 2;   // group 0..7
    const int tg   = lane & 3;    // 0..3
    const int wm   = w & 1;       // 2 warps in M
    const int wn   = w >> 1;      // 4 warps in N
    const int bm0  = blockIdx.y * 128;
    const int bn0  = blockIdx.x * 128;

    const float* Ag = A + (size_t)bm0 * lda;
    const float* Bg = Bw + bn0;

    float acc[4][4][4];
    #pragma unroll
    for (int i = 0; i < 4; i++)
        #pragma unroll
        for (int j = 0; j < 4; j++)
            #pragma unroll
            for (int r = 0; r < 4; r++) acc[i][j][r] = 0.0f;

    load_tiles(sA[0], sB[0], Ag, Bg, lda, t);
    CP_COMMIT();

    for (int kt = 0; kt < KT; kt++) {
        CP_WAIT0();
        __syncthreads();
        if (kt + 1 < KT) {
            load_tiles(sA[(kt + 1) & 1], sB[(kt + 1) & 1],
                       Ag + (kt + 1) * 32, Bg + (size_t)(kt + 1) * 32 * EMBED, lda, t);
            CP_COMMIT();
        }
        const float* As = (const float*)(smem + (size_t)((kt & 1) ? A_BYTES : 0));
        const float* Bs = (const float*)(smem + 2 * A_BYTES + (size_t)((kt & 1) ? B_BYTES : 0));

        #pragma unroll
        for (int ks = 0; ks < 4; ks++) {
            const int k8 = ks * 8;
            uint32_t af[4][4], bf[4][2];
            #pragma unroll
            for (int mt = 0; mt < 4; mt++) {
                const int m = wm * 64 + mt * 16;
                af[mt][0] = __float_as_uint(As[(m + g)     * A_STRIDE + k8 + tg]);
                af[mt][1] = __float_as_uint(As[(m + g + 8) * A_STRIDE + k8 + tg]);
                af[mt][2] = __float_as_uint(As[(m + g)     * A_STRIDE + k8 + tg + 4]);
                af[mt][3] = __float_as_uint(As[(m + g + 8) * A_STRIDE + k8 + tg + 4]);
            }
            #pragma unroll
            for (int nt = 0; nt < 4; nt++) {
                const int n = wn * 32 + nt * 8;
                bf[nt][0] = __float_as_uint(Bs[(k8 + tg)     * B_STRIDE + n + g]);
                bf[nt][1] = __float_as_uint(Bs[(k8 + tg + 4) * B_STRIDE + n + g]);
            }
            #pragma unroll
            for (int mt = 0; mt < 4; mt++)
                #pragma unroll
                for (int nt = 0; nt < 4; nt++)
                    mma_tf32(acc[mt][nt], af[mt], bf[nt]);
        }
        __syncthreads();
    }

    // Epilogue: bias (+GELU) (+tf32 round), float2 stores
    #pragma unroll
    for (int nt = 0; nt < 4; nt++) {
        const int col = bn0 + wn * 32 + nt * 8 + 2 * tg;
        const float2 bb = *(const float2*)(bias + col);
        #pragma unroll
        for (int mt = 0; mt < 4; mt++) {
            const int row = bm0 + wm * 64 + mt * 16 + g;
            #pragma unroll
            for (int h = 0; h < 2; h++) {       // row, row+8
                float2 v;
                v.x = acc[mt][nt][h * 2 + 0] + bb.x;
                v.y = acc[mt][nt][h * 2 + 1] + bb.y;
                if (GELU) {
                    v.x = 0.5f * v.x * (1.0f + erff(v.x * 0.70710678118654752f));
                    v.y = 0.5f * v.y * (1.0f + erff(v.y * 0.70710678118654752f));
                }
                if (ROUND_OUT) { v.x = to_tf32(v.x); v.y = to_tf32(v.y); }
                *(float2*)(C + (size_t)(row + h * 8) * EMBED + col) = v;
            }
        }
    }
}

// ---------------------------------------------------------------------------
extern "C" void kernel_launch(void* const* d_in, const int* in_sizes, int n_in,
                              void* d_out, int out_size)
{
    const float* frames = (const float*)d_in[0];
    const float* coords = (const float*)d_in[1];
    const int*   t_src  = (const int*)  d_in[2];
    const float* W1     = (const float*)d_in[3];
    const float* b1     = (const float*)d_in[4];
    const float* W2     = (const float*)d_in[5];
    const float* b2     = (const float*)d_in[6];
    float*       out    = (float*)d_out;

    float *X, *H, *W1R, *W2R;
    cudaGetSymbolAddress((void**)&X,   g_X);
    cudaGetSymbolAddress((void**)&H,   g_H);
    cudaGetSymbolAddress((void**)&W1R, g_W1R);
    cudaGetSymbolAddress((void**)&W2R, g_W2R);

    cudaFuncSetAttribute(gemm_mma<true, true>,   cudaFuncAttributeMaxDynamicSharedMemorySize, S_TOTAL);
    cudaFuncSetAttribute(gemm_mma<false, false>, cudaFuncAttributeMaxDynamicSharedMemorySize, S_TOTAL);

    gather_kernel<<<M_ROWS, 256>>>(frames, coords, t_src);
    round_w1_clean<<<(KPAD * EMBED + 255) / 256, 256>>>(W1);
    round_w2<<<(EMBED * EMBED + 255) / 256, 256>>>(W2);

    dim3 grid(EMBED / 128, M_ROWS / 128);   // (6, 256), x fastest -> A tiles L2-shared
    gemm_mma<true, true>  <<<grid, 256, S_TOTAL>>>(X, W1R, b1, H,   KPAD  / 32, KPAD);
    gemm_mma<false, false><<<grid, 256, S_TOTAL>>>(H, W2R, b2, out, EMBED / 32, EMBED);
}

// round 4
// speedup vs baseline: 3.9028x; 1.1687x over previous
#include <cuda_runtime.h>
#include <math.h>
#include <stdint.h>

// Problem constants
#define B_SZ   4
#define T_SZ   16
#define C_SZ   3
#define H_SZ   256
#define W_SZ   256
#define N_PTS  8192
#define PATCH  9
#define EMBED  768
#define PDIM   243
#define KPAD   256
#define M_ROWS 32768

// Scratch (__device__ globals: allocation-free rule)
__device__ float g_X[(size_t)M_ROWS * KPAD];     // gathered patches, tf32-rounded, K-padded
__device__ float g_H[(size_t)M_ROWS * EMBED];    // hidden, tf32-rounded
__device__ float g_W1T[(size_t)EMBED * KPAD];    // W1^T [768][256], tf32, K-padded
__device__ float g_W2T[(size_t)EMBED * EMBED];   // W2^T [768][768], tf32

__device__ __forceinline__ float to_tf32(float x) {
    float y; asm("cvt.rna.tf32.f32 %0, %1;" : "=f"(y) : "f"(x)); return y;
}
__device__ __forceinline__ uint32_t smem_u32(const void* p) {
    uint32_t a;
    asm("{ .reg .u64 t; cvta.to.shared.u64 t, %1; cvt.u32.u64 %0, t; }" : "=r"(a) : "l"(p));
    return a;
}
__device__ __forceinline__ void cp16(uint32_t dst, const void* src) {
    asm volatile("cp.async.cg.shared.global [%0], [%1], 16;" :: "r"(dst), "l"(src));
}
#define CP_COMMIT() asm volatile("cp.async.commit_group;" ::: "memory")
#define CP_WAIT0()  asm volatile("cp.async.wait_group 0;" ::: "memory")

__device__ __forceinline__ void mma_tf32(float* c, const uint32_t* a, const uint32_t* b) {
    asm volatile(
        "mma.sync.aligned.m16n8k8.row.col.f32.tf32.tf32.f32 "
        "{%0,%1,%2,%3}, {%4,%5,%6,%7}, {%8,%9}, {%0,%1,%2,%3};"
        : "+f"(c[0]), "+f"(c[1]), "+f"(c[2]), "+f"(c[3])
        : "r"(a[0]), "r"(a[1]), "r"(a[2]), "r"(a[3]), "r"(b[0]), "r"(b[1]));
}
__device__ __forceinline__ void ldm_x4(uint32_t* r, uint32_t addr) {
    asm volatile("ldmatrix.sync.aligned.m8n8.x4.shared.b16 {%0,%1,%2,%3}, [%4];"
        : "=r"(r[0]), "=r"(r[1]), "=r"(r[2]), "=r"(r[3]) : "r"(addr));
}
__device__ __forceinline__ void ldm_x2(uint32_t* r, uint32_t addr) {
    asm volatile("ldmatrix.sync.aligned.m8n8.x2.shared.b16 {%0,%1}, [%2];"
        : "=r"(r[0]), "=r"(r[1]) : "r"(addr));
}

// ---------------------------------------------------------------------------
// Gather patches -> g_X (tf32-rounded, cols 243..255 zero)
// ---------------------------------------------------------------------------
__global__ __launch_bounds__(256) void gather_kernel(
    const float* __restrict__ frames,
    const float* __restrict__ coords,
    const int*   __restrict__ t_src)
{
    int row = blockIdx.x;
    int col = threadIdx.x;
    int b = row >> 13;
    int n = row & (N_PTS - 1);

    float val = 0.0f;
    if (col < PDIM) {
        int c  = col % 3;
        int p  = col / 3;
        int dx = p % PATCH;
        int dy = p / PATCH;
        float cu = coords[(size_t)(b * N_PTS + n) * 2 + 0];
        float cv = coords[(size_t)(b * N_PTS + n) * 2 + 1];
        int u = (int)(cu * (float)(W_SZ - 1));
        int v = (int)(cv * (float)(H_SZ - 1));
        int t = t_src[b * N_PTS + n];
        int y = min(max(v + dy - PATCH / 2, 0), H_SZ - 1);
        int x = min(max(u + dx - PATCH / 2, 0), W_SZ - 1);
        val = to_tf32(frames[((((size_t)b * T_SZ + t) * C_SZ + c) * H_SZ + y) * W_SZ + x]);
    }
    g_X[(size_t)row * KPAD + col] = val;
}

// ---------------------------------------------------------------------------
// Tiled weight transposes (tf32-rounded). out[n][k] = tf32(in[k][n]); pad k.
// ---------------------------------------------------------------------------
__global__ __launch_bounds__(256) void transpose_round(
    const float* __restrict__ in, float* __restrict__ out,
    int Kin, int Kout, int Nn)   // in: [Kin][Nn], out: [Nn][Kout]
{
    __shared__ float tile[32][33];
    int k0 = blockIdx.y * 32;
    int n0 = blockIdx.x * 32;
    int tx = threadIdx.x & 31;
    int ty = threadIdx.x >> 5;    // 0..7
    #pragma unroll
    for (int i = 0; i < 4; i++) {
        int k = k0 + ty + i * 8;
        tile[ty + i * 8][tx] = (k < Kin) ? to_tf32(in[(size_t)k * Nn + n0 + tx]) : 0.0f;
    }
    __syncthreads();
    #pragma unroll
    for (int i = 0; i < 4; i++) {
        int n = n0 + ty + i * 8;
        out[(size_t)n * Kout + k0 + tx] = tile[tx][ty + i * 8];
    }
}

// ---------------------------------------------------------------------------
// TF32 mma.sync GEMM with ldmatrix operand fetch.
// C[M][768] = act(A[M][lda] * BT[768][ldb]^T + bias)
// BM=128 BN=128 BK=32; 256 thr, warps 2M x 4N, warp tile 64x32.
// Both smem tiles: 128 rows x 128B, SW128 swizzle (granule q ^= row&7).
// ---------------------------------------------------------------------------
#define TILE_BYTES 16384
#define S_TOTAL    (4 * TILE_BYTES)   // A0 A1 B0 B1 = 64KB

__device__ __forceinline__ void load_tile(uint32_t sdst,
                                          const float* __restrict__ src,
                                          int lds, int t)
{
    #pragma unroll
    for (int i = 0; i < 4; i++) {
        int li = t + 256 * i;         // 0..1023 granules
        int row = li >> 3;
        int q   = li & 7;
        cp16(sdst + row * 128 + ((q ^ (row & 7)) << 4),
             src + (size_t)row * lds + q * 4);
    }
}

template<bool GELU, bool ROUND_OUT>
__global__ void __launch_bounds__(256, 2) gemm_mma(
    const float* __restrict__ A,    // [M][lda]
    const float* __restrict__ BT,   // [768][ldb]  (N-major, K contiguous)
    const float* __restrict__ bias,
    float* __restrict__ C,          // [M][768]
    int KT, int lda, int ldb)
{
    extern __shared__ __align__(1024) char smem[];
    const uint32_t sb = smem_u32(smem);
    const uint32_t sA[2] = { sb,                  sb + TILE_BYTES };
    const uint32_t sB[2] = { sb + 2 * TILE_BYTES, sb + 3 * TILE_BYTES };

    const int t    = threadIdx.x;
    const int w    = t >> 5;
    const int lane = t & 31;
    const int wm   = w & 1;
    const int wn   = w >> 1;
    const int bm0  = blockIdx.y * 128;
    const int bn0  = blockIdx.x * 128;

    // ldmatrix lane-address components
    const int rA_lane = ((lane >> 3) & 1) * 8 + (lane & 7);  // row within 16-row frag
    const int khA     = lane >> 4;                           // k granule half (0/1)
    const int rB_lane = lane & 7;
    const int khB     = (lane >> 3) & 1;

    // Per-mt/nt row offsets (bytes) and swizzle keys
    int offA[4], xA[4];
    #pragma unroll
    for (int mt = 0; mt < 4; mt++) {
        int row = wm * 64 + mt * 16 + rA_lane;
        offA[mt] = row * 128;
        xA[mt]   = row & 7;
    }
    int offB[4], xB[4];
    #pragma unroll
    for (int nt = 0; nt < 4; nt++) {
        int row = wn * 32 + nt * 8 + rB_lane;
        offB[nt] = row * 128;
        xB[nt]   = row & 7;
    }

    const float* Ag = A  + (size_t)bm0 * lda;
    const float* Bg = BT + (size_t)bn0 * ldb;

    float acc[4][4][4];
    #pragma unroll
    for (int i = 0; i < 4; i++)
        #pragma unroll
        for (int j = 0; j < 4; j++)
            #pragma unroll
            for (int r = 0; r < 4; r++) acc[i][j][r] = 0.0f;

    load_tile(sA[0], Ag, lda, t);
    load_tile(sB[0], Bg, ldb, t);
    CP_COMMIT();

    for (int kt = 0; kt < KT; kt++) {
        CP_WAIT0();
        __syncthreads();
        if (kt + 1 < KT) {
            load_tile(sA[(kt + 1) & 1], Ag + (kt + 1) * 32, lda, t);
            load_tile(sB[(kt + 1) & 1], Bg + (kt + 1) * 32, ldb, t);
            CP_COMMIT();
        }
        const uint32_t a_base = sA[kt & 1];
        const uint32_t b_base = sB[kt & 1];

        #pragma unroll
        for (int ks = 0; ks < 4; ks++) {
            uint32_t af[4][4], bf[4][2];
            #pragma unroll
            for (int mt = 0; mt < 4; mt++)
                ldm_x4(af[mt], a_base + offA[mt] + (((ks * 2 + khA) ^ xA[mt]) << 4));
            #pragma unroll
            for (int nt = 0; nt < 4; nt++)
                ldm_x2(bf[nt], b_base + offB[nt] + (((ks * 2 + khB) ^ xB[nt]) << 4));
            #pragma unroll
            for (int mt = 0; mt < 4; mt++)
                #pragma unroll
                for (int nt = 0; nt < 4; nt++)
                    mma_tf32(acc[mt][nt], af[mt], bf[nt]);
        }
        __syncthreads();
    }

    // Epilogue
    const int g  = lane >> 2;
    const int tg = lane & 3;
    #pragma unroll
    for (int nt = 0; nt < 4; nt++) {
        const int col = bn0 + wn * 32 + nt * 8 + 2 * tg;
        const float2 bb = *(const float2*)(bias + col);
        #pragma unroll
        for (int mt = 0; mt < 4; mt++) {
            const int row = bm0 + wm * 64 + mt * 16 + g;
            #pragma unroll
            for (int h = 0; h < 2; h++) {
                float2 v;
                v.x = acc[mt][nt][h * 2 + 0] + bb.x;
                v.y = acc[mt][nt][h * 2 + 1] + bb.y;
                if (GELU) {
                    v.x = 0.5f * v.x * (1.0f + erff(v.x * 0.70710678118654752f));
                    v.y = 0.5f * v.y * (1.0f + erff(v.y * 0.70710678118654752f));
                }
                if (ROUND_OUT) { v.x = to_tf32(v.x); v.y = to_tf32(v.y); }
                *(float2*)(C + (size_t)(row + h * 8) * EMBED + col) = v;
            }
        }
    }
}

// ---------------------------------------------------------------------------
extern "C" void kernel_launch(void* const* d_in, const int* in_sizes, int n_in,
                              void* d_out, int out_size)
{
    const float* frames = (const float*)d_in[0];
    const float* coords = (const float*)d_in[1];
    const int*   t_src  = (const int*)  d_in[2];
    const float* W1     = (const float*)d_in[3];
    const float* b1     = (const float*)d_in[4];
    const float* W2     = (const float*)d_in[5];
    const float* b2     = (const float*)d_in[6];
    float*       out    = (float*)d_out;

    float *X, *H, *W1T, *W2T;
    cudaGetSymbolAddress((void**)&X,   g_X);
    cudaGetSymbolAddress((void**)&H,   g_H);
    cudaGetSymbolAddress((void**)&W1T, g_W1T);
    cudaGetSymbolAddress((void**)&W2T, g_W2T);

    cudaFuncSetAttribute(gemm_mma<true, true>,   cudaFuncAttributeMaxDynamicSharedMemorySize, S_TOTAL);
    cudaFuncSetAttribute(gemm_mma<false, false>, cudaFuncAttributeMaxDynamicSharedMemorySize, S_TOTAL);

    gather_kernel<<<M_ROWS, 256>>>(frames, coords, t_src);
    {
        dim3 g1(EMBED / 32, KPAD / 32);
        transpose_round<<<g1, 256>>>(W1, W1T, PDIM, KPAD, EMBED);
        dim3 g2(EMBED / 32, EMBED / 32);
        transpose_round<<<g2, 256>>>(W2, W2T, EMBED, EMBED, EMBED);
    }

    dim3 grid(EMBED / 128, M_ROWS / 128);   // (6, 256), x fastest -> A tiles L2-shared
    gemm_mma<true, true>  <<<grid, 256, S_TOTAL>>>(X, W1T, b1, H,   KPAD  / 32, KPAD,  KPAD);
    gemm_mma<false, false><<<grid, 256, S_TOTAL>>>(H, W2T, b2, out, EMBED / 32, EMBED, EMBED);
}

// round 5
// speedup vs baseline: 5.9501x; 1.5246x over previous
#include <cuda_runtime.h>
#include <cuda_fp16.h>
#include <math.h>
#include <stdint.h>

// Problem constants
#define B_SZ   4
#define T_SZ   16
#define C_SZ   3
#define H_SZ   256
#define W_SZ   256
#define N_PTS  8192
#define PATCH  9
#define EMBED  768
#define PDIM   243
#define KPAD   256
#define M_ROWS 32768

// Scratch (__device__ globals: allocation-free rule)
__device__ __half g_X[(size_t)M_ROWS * KPAD];     // gathered patches, fp16, K-padded
__device__ __half g_H[(size_t)M_ROWS * EMBED];    // hidden, fp16
__device__ __half g_W1T[(size_t)EMBED * KPAD];    // W1^T [768][256], fp16, K-padded
__device__ __half g_W2T[(size_t)EMBED * EMBED];   // W2^T [768][768], fp16

__device__ __forceinline__ uint32_t smem_u32(const void* p) {
    uint32_t a;
    asm("{ .reg .u64 t; cvta.to.shared.u64 t, %1; cvt.u32.u64 %0, t; }" : "=r"(a) : "l"(p));
    return a;
}
__device__ __forceinline__ void cp16(uint32_t dst, const void* src) {
    asm volatile("cp.async.cg.shared.global [%0], [%1], 16;" :: "r"(dst), "l"(src));
}
#define CP_COMMIT() asm volatile("cp.async.commit_group;" ::: "memory")
#define CP_WAIT0()  asm volatile("cp.async.wait_group 0;" ::: "memory")

__device__ __forceinline__ void mma_f16(float* c, const uint32_t* a, const uint32_t* b) {
    asm volatile(
        "mma.sync.aligned.m16n8k16.row.col.f32.f16.f16.f32 "
        "{%0,%1,%2,%3}, {%4,%5,%6,%7}, {%8,%9}, {%0,%1,%2,%3};"
        : "+f"(c[0]), "+f"(c[1]), "+f"(c[2]), "+f"(c[3])
        : "r"(a[0]), "r"(a[1]), "r"(a[2]), "r"(a[3]), "r"(b[0]), "r"(b[1]));
}
__device__ __forceinline__ void ldm_x4(uint32_t* r, uint32_t addr) {
    asm volatile("ldmatrix.sync.aligned.m8n8.x4.shared.b16 {%0,%1,%2,%3}, [%4];"
        : "=r"(r[0]), "=r"(r[1]), "=r"(r[2]), "=r"(r[3]) : "r"(addr));
}
__device__ __forceinline__ void ldm_x2(uint32_t* r, uint32_t addr) {
    asm volatile("ldmatrix.sync.aligned.m8n8.x2.shared.b16 {%0,%1}, [%2];"
        : "=r"(r[0]), "=r"(r[1]) : "r"(addr));
}

// ---------------------------------------------------------------------------
// Gather patches -> g_X fp16 (cols 243..255 zero)
// ---------------------------------------------------------------------------
__global__ __launch_bounds__(256) void gather_kernel(
    const float* __restrict__ frames,
    const float* __restrict__ coords,
    const int*   __restrict__ t_src)
{
    int row = blockIdx.x;
    int col = threadIdx.x;
    int b = row >> 13;
    int n = row & (N_PTS - 1);

    float val = 0.0f;
    if (col < PDIM) {
        int c  = col % 3;
        int p  = col / 3;
        int dx = p % PATCH;
        int dy = p / PATCH;
        float cu = coords[(size_t)(b * N_PTS + n) * 2 + 0];
        float cv = coords[(size_t)(b * N_PTS + n) * 2 + 1];
        int u = (int)(cu * (float)(W_SZ - 1));
        int v = (int)(cv * (float)(H_SZ - 1));
        int t = t_src[b * N_PTS + n];
        int y = min(max(v + dy - PATCH / 2, 0), H_SZ - 1);
        int x = min(max(u + dx - PATCH / 2, 0), W_SZ - 1);
        val = frames[((((size_t)b * T_SZ + t) * C_SZ + c) * H_SZ + y) * W_SZ + x];
    }
    g_X[(size_t)row * KPAD + col] = __float2half_rn(val);
}

// ---------------------------------------------------------------------------
// Tiled weight transpose to fp16. out[n][k] = h(in[k][n]); k-pad with zeros.
// ---------------------------------------------------------------------------
__global__ __launch_bounds__(256) void transpose_h(
    const float* __restrict__ in, __half* __restrict__ out,
    int Kin, int Kout, int Nn)   // in: [Kin][Nn], out: [Nn][Kout]
{
    __shared__ float tile[32][33];
    int k0 = blockIdx.y * 32;
    int n0 = blockIdx.x * 32;
    int tx = threadIdx.x & 31;
    int ty = threadIdx.x >> 5;
    #pragma unroll
    for (int i = 0; i < 4; i++) {
        int k = k0 + ty + i * 8;
        tile[ty + i * 8][tx] = (k < Kin) ? in[(size_t)k * Nn + n0 + tx] : 0.0f;
    }
    __syncthreads();
    #pragma unroll
    for (int i = 0; i < 4; i++) {
        int n = n0 + ty + i * 8;
        out[(size_t)n * Kout + k0 + tx] = __float2half_rn(tile[tx][ty + i * 8]);
    }
}

// ---------------------------------------------------------------------------
// FP16 mma.sync m16n8k16 GEMM with ldmatrix operand fetch.
// C[M][768] = act(A[M][lda] * BT[768][ldb]^T + bias)
// BM=128 BN=128 BK=64 (halves); 256 thr, warps 2M x 4N, warp tile 64x32.
// smem tiles: 128 rows x 128B (64 halves), SW128 swizzle (granule ^ row&7).
// ---------------------------------------------------------------------------
#define TILE_BYTES 16384
#define S_TOTAL    (4 * TILE_BYTES)   // A0 A1 B0 B1 = 64KB

__device__ __forceinline__ void load_tile(uint32_t sdst,
                                          const __half* __restrict__ src,
                                          int lds, int t)
{
    #pragma unroll
    for (int i = 0; i < 4; i++) {
        int li = t + 256 * i;         // 0..1023 granules (128 rows x 8)
        int row = li >> 3;
        int q   = li & 7;             // 16B granule = 8 halves (k8 chunk)
        cp16(sdst + row * 128 + ((q ^ (row & 7)) << 4),
             src + (size_t)row * lds + q * 8);
    }
}

template<bool GELU, typename OutT>
__global__ void __launch_bounds__(256, 2) gemm_mma(
    const __half* __restrict__ A,    // [M][lda]
    const __half* __restrict__ BT,   // [768][ldb]  (N-major, K contiguous)
    const float*  __restrict__ bias,
    OutT* __restrict__ C,            // [M][768]
    int KT, int lda, int ldb)
{
    extern __shared__ __align__(1024) char smem[];
    const uint32_t sb = smem_u32(smem);
    const uint32_t sA[2] = { sb,                  sb + TILE_BYTES };
    const uint32_t sB[2] = { sb + 2 * TILE_BYTES, sb + 3 * TILE_BYTES };

    const int t    = threadIdx.x;
    const int w    = t >> 5;
    const int lane = t & 31;
    const int wm   = w & 1;
    const int wn   = w >> 1;
    const int bm0  = blockIdx.y * 128;
    const int bn0  = blockIdx.x * 128;

    // ldmatrix lane-address components (16B granule = k 8-chunk)
    const int rA_lane = ((lane >> 3) & 1) * 8 + (lane & 7);
    const int khA     = lane >> 4;           // which k8 granule within k16 slice
    const int rB_lane = lane & 7;
    const int khB     = (lane >> 3) & 1;

    int offA[4], xA[4];
    #pragma unroll
    for (int mt = 0; mt < 4; mt++) {
        int row = wm * 64 + mt * 16 + rA_lane;
        offA[mt] = row * 128;
        xA[mt]   = row & 7;
    }
    int offB[4], xB[4];
    #pragma unroll
    for (int nt = 0; nt < 4; nt++) {
        int row = wn * 32 + nt * 8 + rB_lane;
        offB[nt] = row * 128;
        xB[nt]   = row & 7;
    }

    const __half* Ag = A  + (size_t)bm0 * lda;
    const __half* Bg = BT + (size_t)bn0 * ldb;

    float acc[4][4][4];
    #pragma unroll
    for (int i = 0; i < 4; i++)
        #pragma unroll
        for (int j = 0; j < 4; j++)
            #pragma unroll
            for (int r = 0; r < 4; r++) acc[i][j][r] = 0.0f;

    load_tile(sA[0], Ag, lda, t);
    load_tile(sB[0], Bg, ldb, t);
    CP_COMMIT();

    for (int kt = 0; kt < KT; kt++) {
        CP_WAIT0();
        __syncthreads();
        if (kt + 1 < KT) {
            load_tile(sA[(kt + 1) & 1], Ag + (size_t)(kt + 1) * 64, lda, t);
            load_tile(sB[(kt + 1) & 1], Bg + (size_t)(kt + 1) * 64, ldb, t);
            CP_COMMIT();
        }
        const uint32_t a_base = sA[kt & 1];
        const uint32_t b_base = sB[kt & 1];

        #pragma unroll
        for (int ks = 0; ks < 4; ks++) {       // 4 k16-slices per BK=64
            uint32_t af[4][4], bf[4][2];
            #pragma unroll
            for (int mt = 0; mt < 4; mt++)
                ldm_x4(af[mt], a_base + offA[mt] + (((ks * 2 + khA) ^ xA[mt]) << 4));
            #pragma unroll
            for (int nt = 0; nt < 4; nt++)
                ldm_x2(bf[nt], b_base + offB[nt] + (((ks * 2 + khB) ^ xB[nt]) << 4));
            #pragma unroll
            for (int mt = 0; mt < 4; mt++)
                #pragma unroll
                for (int nt = 0; nt < 4; nt++)
                    mma_f16(acc[mt][nt], af[mt], bf[nt]);
        }
        __syncthreads();
    }

    // Epilogue: bias (+GELU), pairwise stores (half2 or float2)
    const int g  = lane >> 2;
    const int tg = lane & 3;
    #pragma unroll
    for (int nt = 0; nt < 4; nt++) {
        const int col = bn0 + wn * 32 + nt * 8 + 2 * tg;
        const float2 bb = *(const float2*)(bias + col);
        #pragma unroll
        for (int mt = 0; mt < 4; mt++) {
            const int row = bm0 + wm * 64 + mt * 16 + g;
            #pragma unroll
            for (int h = 0; h < 2; h++) {
                float vx = acc[mt][nt][h * 2 + 0] + bb.x;
                float vy = acc[mt][nt][h * 2 + 1] + bb.y;
                if (GELU) {
                    vx = 0.5f * vx * (1.0f + erff(vx * 0.70710678118654752f));
                    vy = 0.5f * vy * (1.0f + erff(vy * 0.70710678118654752f));
                }
                OutT* dst = C + (size_t)(row + h * 8) * EMBED + col;
                if (sizeof(OutT) == 2) {
                    *(__half2*)dst = __floats2half2_rn(vx, vy);
                } else {
                    *(float2*)dst = make_float2(vx, vy);
                }
            }
        }
    }
}

// ---------------------------------------------------------------------------
extern "C" void kernel_launch(void* const* d_in, const int* in_sizes, int n_in,
                              void* d_out, int out_size)
{
    const float* frames = (const float*)d_in[0];
    const float* coords = (const float*)d_in[1];
    const int*   t_src  = (const int*)  d_in[2];
    const float* W1     = (const float*)d_in[3];
    const float* b1     = (const float*)d_in[4];
    const float* W2     = (const float*)d_in[5];
    const float* b2     = (const float*)d_in[6];
    float*       out    = (float*)d_out;

    __half *X, *H, *W1T, *W2T;
    cudaGetSymbolAddress((void**)&X,   g_X);
    cudaGetSymbolAddress((void**)&H,   g_H);
    cudaGetSymbolAddress((void**)&W1T, g_W1T);
    cudaGetSymbolAddress((void**)&W2T, g_W2T);

    cudaFuncSetAttribute(gemm_mma<true,  __half>, cudaFuncAttributeMaxDynamicSharedMemorySize, S_TOTAL);
    cudaFuncSetAttribute(gemm_mma<false, float>,  cudaFuncAttributeMaxDynamicSharedMemorySize, S_TOTAL);

    gather_kernel<<<M_ROWS, 256>>>(frames, coords, t_src);
    {
        dim3 g1(EMBED / 32, KPAD / 32);
        transpose_h<<<g1, 256>>>(W1, W1T, PDIM, KPAD, EMBED);
        dim3 g2(EMBED / 32, EMBED / 32);
        transpose_h<<<g2, 256>>>(W2, W2T, EMBED, EMBED, EMBED);
    }

    dim3 grid(EMBED / 128, M_ROWS / 128);   // (6, 256)
    gemm_mma<true,  __half><<<grid, 256, S_TOTAL>>>(X, W1T, b1, H,   KPAD  / 64, KPAD,  KPAD);
    gemm_mma<false, float> <<<grid, 256, S_TOTAL>>>(H, W2T, b2, out, EMBED / 64, EMBED, EMBED);
}

// round 6
// speedup vs baseline: 6.1341x; 1.0309x over previous
#include <cuda_runtime.h>
#include <cuda_fp16.h>
#include <math.h>
#include <stdint.h>

// Problem constants
#define B_SZ   4
#define T_SZ   16
#define C_SZ   3
#define H_SZ   256
#define W_SZ   256
#define N_PTS  8192
#define PATCH  9
#define EMBED  768
#define PDIM   243
#define KPAD   256
#define M_ROWS 32768

// Scratch (__device__ globals: allocation-free rule)
__device__ __half g_X[(size_t)M_ROWS * KPAD];
__device__ __half g_H[(size_t)M_ROWS * EMBED];
__device__ __half g_W1T[(size_t)EMBED * KPAD];
__device__ __half g_W2T[(size_t)EMBED * EMBED];

__device__ __forceinline__ uint32_t smem_u32(const void* p) {
    uint32_t a;
    asm("{ .reg .u64 t; cvta.to.shared.u64 t, %1; cvt.u32.u64 %0, t; }" : "=r"(a) : "l"(p));
    return a;
}
__device__ __forceinline__ void cp16(uint32_t dst, const void* src) {
    asm volatile("cp.async.cg.shared.global [%0], [%1], 16;" :: "r"(dst), "l"(src));
}
#define CP_COMMIT() asm volatile("cp.async.commit_group;" ::: "memory")
#define CP_WAIT0()  asm volatile("cp.async.wait_group 0;" ::: "memory")

__device__ __forceinline__ void mma_f16(float* c, const uint32_t* a, const uint32_t* b) {
    asm volatile(
        "mma.sync.aligned.m16n8k16.row.col.f32.f16.f16.f32 "
        "{%0,%1,%2,%3}, {%4,%5,%6,%7}, {%8,%9}, {%0,%1,%2,%3};"
        : "+f"(c[0]), "+f"(c[1]), "+f"(c[2]), "+f"(c[3])
        : "r"(a[0]), "r"(a[1]), "r"(a[2]), "r"(a[3]), "r"(b[0]), "r"(b[1]));
}
__device__ __forceinline__ void ldm_x4(uint32_t* r, uint32_t addr) {
    asm volatile("ldmatrix.sync.aligned.m8n8.x4.shared.b16 {%0,%1,%2,%3}, [%4];"
        : "=r"(r[0]), "=r"(r[1]), "=r"(r[2]), "=r"(r[3]) : "r"(addr));
}

// ---------------------------------------------------------------------------
// Gather patches -> g_X fp16 (cols 243..255 zero)
// ---------------------------------------------------------------------------
__global__ __launch_bounds__(256) void gather_kernel(
    const float* __restrict__ frames,
    const float* __restrict__ coords,
    const int*   __restrict__ t_src)
{
    int row = blockIdx.x;
    int col = threadIdx.x;
    int b = row >> 13;
    int n = row & (N_PTS - 1);

    float val = 0.0f;
    if (col < PDIM) {
        int c  = col % 3;
        int p  = col / 3;
        int dx = p % PATCH;
        int dy = p / PATCH;
        float cu = coords[(size_t)(b * N_PTS + n) * 2 + 0];
        float cv = coords[(size_t)(b * N_PTS + n) * 2 + 1];
        int u = (int)(cu * (float)(W_SZ - 1));
        int v = (int)(cv * (float)(H_SZ - 1));
        int t = t_src[b * N_PTS + n];
        int y = min(max(v + dy - PATCH / 2, 0), H_SZ - 1);
        int x = min(max(u + dx - PATCH / 2, 0), W_SZ - 1);
        val = frames[((((size_t)b * T_SZ + t) * C_SZ + c) * H_SZ + y) * W_SZ + x];
    }
    g_X[(size_t)row * KPAD + col] = __float2half_rn(val);
}

// ---------------------------------------------------------------------------
// Tiled weight transpose to fp16. out[n][k] = h(in[k][n]); k-pad with zeros.
// ---------------------------------------------------------------------------
__global__ __launch_bounds__(256) void transpose_h(
    const float* __restrict__ in, __half* __restrict__ out,
    int Kin, int Kout, int Nn)
{
    __shared__ float tile[32][33];
    int k0 = blockIdx.y * 32;
    int n0 = blockIdx.x * 32;
    int tx = threadIdx.x & 31;
    int ty = threadIdx.x >> 5;
    #pragma unroll
    for (int i = 0; i < 4; i++) {
        int k = k0 + ty + i * 8;
        tile[ty + i * 8][tx] = (k < Kin) ? in[(size_t)k * Nn + n0 + tx] : 0.0f;
    }
    __syncthreads();
    #pragma unroll
    for (int i = 0; i < 4; i++) {
        int n = n0 + ty + i * 8;
        out[(size_t)n * Kout + k0 + tx] = __float2half_rn(tile[tx][ty + i * 8]);
    }
}

// ---------------------------------------------------------------------------
// FP16 m16n8k16 GEMM, ldmatrix.x4 for A and paired-B; compile-time KT.
// BM=128 BN=128 BK=64; 256 thr, warps 2M x 4N, warp tile 64x32.
// smem tiles: 128 rows x 128B, SW128-style swizzle (granule ^ row&7).
// ---------------------------------------------------------------------------
#define TILE_BYTES 16384
#define S_TOTAL    (4 * TILE_BYTES)

__device__ __forceinline__ void load_tile(uint32_t sdst,
                                          const __half* __restrict__ src,
                                          int lds, int t)
{
    #pragma unroll
    for (int i = 0; i < 4; i++) {
        int li = t + 256 * i;
        int row = li >> 3;
        int q   = li & 7;
        cp16(sdst + row * 128 + ((q ^ (row & 7)) << 4),
             src + (size_t)row * lds + q * 8);
    }
}

template<int KT, bool GELU, typename OutT>
__global__ void __launch_bounds__(256, 2) gemm_mma(
    const __half* __restrict__ A,    // [M][lda]
    const __half* __restrict__ BT,   // [768][ldb]
    const float*  __restrict__ bias,
    OutT* __restrict__ C,            // [M][768]
    int lda, int ldb)
{
    extern __shared__ __align__(1024) char smem[];
    const uint32_t sb = smem_u32(smem);

    const int t    = threadIdx.x;
    const int w    = t >> 5;
    const int lane = t & 31;
    const int wm   = w & 1;
    const int wn   = w >> 1;
    const int bm0  = blockIdx.y * 128;
    const int bn0  = blockIdx.x * 128;

    // A frag addressing: row-select bit3, k-granule bit4
    const int rA = ((lane >> 3) & 1) * 8 + (lane & 7);
    const int kA = lane >> 4;
    // B paired-x4 addressing: row-select bit4, k-granule bit3
    const int rB = ((lane >> 4) & 1) * 8 + (lane & 7);
    const int kB = (lane >> 3) & 1;

    int offA[4], xA[4];              // per mt (16-row frags)
    #pragma unroll
    for (int mt = 0; mt < 4; mt++) {
        int row = wm * 64 + mt * 16 + rA;
        offA[mt] = row * 128;
        xA[mt]   = row & 7;
    }
    int offB[2], xB[2];              // per nt-pair (16-row pair frags)
    #pragma unroll
    for (int p = 0; p < 2; p++) {
        int row = wn * 32 + p * 16 + rB;
        offB[p] = row * 128;
        xB[p]   = row & 7;
    }

    const __half* Ag = A  + (size_t)bm0 * lda;
    const __half* Bg = BT + (size_t)bn0 * ldb;

    float acc[4][4][4];
    #pragma unroll
    for (int i = 0; i < 4; i++)
        #pragma unroll
        for (int j = 0; j < 4; j++)
            #pragma unroll
            for (int r = 0; r < 4; r++) acc[i][j][r] = 0.0f;

    load_tile(sb,                  Ag, lda, t);
    load_tile(sb + 2 * TILE_BYTES, Bg, ldb, t);
    CP_COMMIT();

    #pragma unroll 2
    for (int kt = 0; kt < KT; kt++) {
        CP_WAIT0();
        __syncthreads();
        if (kt + 1 < KT) {
            load_tile(sb + ((kt + 1) & 1) * TILE_BYTES,
                      Ag + (size_t)(kt + 1) * 64, lda, t);
            load_tile(sb + 2 * TILE_BYTES + ((kt + 1) & 1) * TILE_BYTES,
                      Bg + (size_t)(kt + 1) * 64, ldb, t);
            CP_COMMIT();
        }
        const uint32_t a_base = sb + (kt & 1) * TILE_BYTES;
        const uint32_t b_base = sb + 2 * TILE_BYTES + (kt & 1) * TILE_BYTES;

        #pragma unroll
        for (int ks = 0; ks < 4; ks++) {
            uint32_t af[4][4], bf[4][2];
            #pragma unroll
            for (int mt = 0; mt < 4; mt++)
                ldm_x4(af[mt], a_base + offA[mt] + (((ks * 2 + kA) ^ xA[mt]) << 4));
            #pragma unroll
            for (int p = 0; p < 2; p++) {
                uint32_t r[4];
                ldm_x4(r, b_base + offB[p] + (((ks * 2 + kB) ^ xB[p]) << 4));
                bf[2 * p][0]     = r[0];  // n lo, k0-7
                bf[2 * p][1]     = r[1];  // n lo, k8-15
                bf[2 * p + 1][0] = r[2];  // n hi, k0-7
                bf[2 * p + 1][1] = r[3];  // n hi, k8-15
            }
            #pragma unroll
            for (int mt = 0; mt < 4; mt++)
                #pragma unroll
                for (int nt = 0; nt < 4; nt++)
                    mma_f16(acc[mt][nt], af[mt], bf[nt]);
        }
        // no trailing barrier: top-of-next-iter barrier orders buffer reuse
    }

    // Epilogue: bias (+GELU), pairwise stores
    const int g  = lane >> 2;
    const int tg = lane & 3;
    #pragma unroll
    for (int nt = 0; nt < 4; nt++) {
        const int col = bn0 + wn * 32 + nt * 8 + 2 * tg;
        const float2 bb = *(const float2*)(bias + col);
        #pragma unroll
        for (int mt = 0; mt < 4; mt++) {
            const int row = bm0 + wm * 64 + mt * 16 + g;
            #pragma unroll
            for (int h = 0; h < 2; h++) {
                float vx = acc[mt][nt][h * 2 + 0] + bb.x;
                float vy = acc[mt][nt][h * 2 + 1] + bb.y;
                if (GELU) {
                    vx = 0.5f * vx * (1.0f + erff(vx * 0.70710678118654752f));
                    vy = 0.5f * vy * (1.0f + erff(vy * 0.70710678118654752f));
                }
                OutT* dst = C + (size_t)(row + h * 8) * EMBED + col;
                if (sizeof(OutT) == 2) {
                    *(__half2*)dst = __floats2half2_rn(vx, vy);
                } else {
                    *(float2*)dst = make_float2(vx, vy);
                }
            }
        }
    }
}

// ---------------------------------------------------------------------------
extern "C" void kernel_launch(void* const* d_in, const int* in_sizes, int n_in,
                              void* d_out, int out_size)
{
    const float* frames = (const float*)d_in[0];
    const float* coords = (const float*)d_in[1];
    const int*   t_src  = (const int*)  d_in[2];
    const float* W1     = (const float*)d_in[3];
    const float* b1     = (const float*)d_in[4];
    const float* W2     = (const float*)d_in[5];
    const float* b2     = (const float*)d_in[6];
    float*       out    = (float*)d_out;

    __half *X, *H, *W1T, *W2T;
    cudaGetSymbolAddress((void**)&X,   g_X);
    cudaGetSymbolAddress((void**)&H,   g_H);
    cudaGetSymbolAddress((void**)&W1T, g_W1T);
    cudaGetSymbolAddress((void**)&W2T, g_W2T);

    cudaFuncSetAttribute(gemm_mma<4,  true,  __half>, cudaFuncAttributeMaxDynamicSharedMemorySize, S_TOTAL);
    cudaFuncSetAttribute(gemm_mma<12, false, float>,  cudaFuncAttributeMaxDynamicSharedMemorySize, S_TOTAL);

    gather_kernel<<<M_ROWS, 256>>>(frames, coords, t_src);
    {
        dim3 g1(EMBED / 32, KPAD / 32);
        transpose_h<<<g1, 256>>>(W1, W1T, PDIM, KPAD, EMBED);
        dim3 g2(EMBED / 32, EMBED / 32);
        transpose_h<<<g2, 256>>>(W2, W2T, EMBED, EMBED, EMBED);
    }

    dim3 grid(EMBED / 128, M_ROWS / 128);
    gemm_mma<4,  true,  __half><<<grid, 256, S_TOTAL>>>(X, W1T, b1, H,   KPAD,  KPAD);
    gemm_mma<12, false, float> <<<grid, 256, S_TOTAL>>>(H, W2T, b2, out, EMBED, EMBED);
}

// round 7
// speedup vs baseline: 6.2370x; 1.0168x over previous
#include <cuda_runtime.h>
#include <cuda_fp16.h>
#include <math.h>
#include <stdint.h>

// Problem constants
#define B_SZ   4
#define T_SZ   16
#define C_SZ   3
#define H_SZ   256
#define W_SZ   256
#define N_PTS  8192
#define PATCH  9
#define EMBED  768
#define PDIM   243
#define KPAD   256
#define M_ROWS 32768

// Scratch (__device__ globals: allocation-free rule)
__device__ __half g_X[(size_t)M_ROWS * KPAD];     // K axis PERMUTED: c*81+dy*9+dx
__device__ __half g_H[(size_t)M_ROWS * EMBED];
__device__ __half g_W1T[(size_t)EMBED * KPAD];    // same K permutation
__device__ __half g_W2T[(size_t)EMBED * EMBED];

__device__ __forceinline__ uint32_t smem_u32(const void* p) {
    uint32_t a;
    asm("{ .reg .u64 t; cvta.to.shared.u64 t, %1; cvt.u32.u64 %0, t; }" : "=r"(a) : "l"(p));
    return a;
}
__device__ __forceinline__ void cp16(uint32_t dst, const void* src) {
    asm volatile("cp.async.cg.shared.global [%0], [%1], 16;" :: "r"(dst), "l"(src));
}
#define CP_COMMIT() asm volatile("cp.async.commit_group;" ::: "memory")
#define CP_WAIT0()  asm volatile("cp.async.wait_group 0;" ::: "memory")
#define CP_WAIT1()  asm volatile("cp.async.wait_group 1;" ::: "memory")

__device__ __forceinline__ void mma_f16(float* c, const uint32_t* a, const uint32_t* b) {
    asm volatile(
        "mma.sync.aligned.m16n8k16.row.col.f32.f16.f16.f32 "
        "{%0,%1,%2,%3}, {%4,%5,%6,%7}, {%8,%9}, {%0,%1,%2,%3};"
        : "+f"(c[0]), "+f"(c[1]), "+f"(c[2]), "+f"(c[3])
        : "r"(a[0]), "r"(a[1]), "r"(a[2]), "r"(a[3]), "r"(b[0]), "r"(b[1]));
}
__device__ __forceinline__ void ldm_x4(uint32_t* r, uint32_t addr) {
    asm volatile("ldmatrix.sync.aligned.m8n8.x4.shared.b16 {%0,%1,%2,%3}, [%4];"
        : "=r"(r[0]), "=r"(r[1]), "=r"(r[2]), "=r"(r[3]) : "r"(addr));
}

// ---------------------------------------------------------------------------
// Gather patches -> g_X fp16, K axis in (c, dy, dx) order (dx fastest).
// Consecutive threads -> consecutive x -> coalesced frame reads.
// ---------------------------------------------------------------------------
__global__ __launch_bounds__(256) void gather_kernel(
    const float* __restrict__ frames,
    const float* __restrict__ coords,
    const int*   __restrict__ t_src)
{
    int row = blockIdx.x;
    int col = threadIdx.x;          // permuted K index
    int b = row >> 13;
    int n = row & (N_PTS - 1);

    float val = 0.0f;
    if (col < PDIM) {
        int c  = col / 81;
        int r  = col - c * 81;
        int dy = r / 9;
        int dx = r - dy * 9;

        float cu = coords[(size_t)(b * N_PTS + n) * 2 + 0];
        float cv = coords[(size_t)(b * N_PTS + n) * 2 + 1];
        int u = (int)(cu * (float)(W_SZ - 1));
        int v = (int)(cv * (float)(H_SZ - 1));
        int t = t_src[b * N_PTS + n];
        int y = min(max(v + dy - PATCH / 2, 0), H_SZ - 1);
        int x = min(max(u + dx - PATCH / 2, 0), W_SZ - 1);
        val = frames[((((size_t)b * T_SZ + t) * C_SZ + c) * H_SZ + y) * W_SZ + x];
    }
    g_X[(size_t)row * KPAD + col] = __float2half_rn(val);
}

// ---------------------------------------------------------------------------
// Tiled weight transpose to fp16; optional K-permutation on the source row.
// out[n][k'] = h(in[orig(k')][n]); zero pad k' >= Kin.
// ---------------------------------------------------------------------------
template<bool PERM>
__global__ __launch_bounds__(256) void transpose_h(
    const float* __restrict__ in, __half* __restrict__ out,
    int Kin, int Kout, int Nn)
{
    __shared__ float tile[32][33];
    int k0 = blockIdx.y * 32;
    int n0 = blockIdx.x * 32;
    int tx = threadIdx.x & 31;
    int ty = threadIdx.x >> 5;
    #pragma unroll
    for (int i = 0; i < 4; i++) {
        int kp = k0 + ty + i * 8;      // permuted index
        float v = 0.0f;
        if (kp < Kin) {
            int k = kp;
            if (PERM) {
                int c = kp / 81;
                int r = kp - c * 81;   // dy*9+dx
                k = r * 3 + c;         // original W1 row
            }
            v = in[(size_t)k * Nn + n0 + tx];
        }
        tile[ty + i * 8][tx] = v;
    }
    __syncthreads();
    #pragma unroll
    for (int i = 0; i < 4; i++) {
        int n = n0 + ty + i * 8;
        out[(size_t)n * Kout + k0 + tx] = __float2half_rn(tile[tx][ty + i * 8]);
    }
}

// ---------------------------------------------------------------------------
// FP16 m16n8k16 GEMM, 3-stage cp.async pipeline.
// BM=128 BN=128 BK=64; 256 thr, warps 2M x 4N, warp tile 64x32.
// smem tiles: 128 rows x 128B, swizzle (granule ^ row&7). 3 stages = 96KB.
// ---------------------------------------------------------------------------
#define TILE_BYTES 16384
#define NSTAGE     3
#define S_TOTAL    (2 * NSTAGE * TILE_BYTES)   // 98304

__device__ __forceinline__ void load_tile(uint32_t sdst,
                                          const __half* __restrict__ src,
                                          int lds, int t)
{
    #pragma unroll
    for (int i = 0; i < 4; i++) {
        int li = t + 256 * i;
        int row = li >> 3;
        int q   = li & 7;
        cp16(sdst + row * 128 + ((q ^ (row & 7)) << 4),
             src + (size_t)row * lds + q * 8);
    }
}

template<int KT, bool GELU, typename OutT>
__global__ void __launch_bounds__(256, 2) gemm_mma(
    const __half* __restrict__ A,    // [M][lda]
    const __half* __restrict__ BT,   // [768][ldb]
    const float*  __restrict__ bias,
    OutT* __restrict__ C,            // [M][768]
    int lda, int ldb)
{
    extern __shared__ __align__(1024) char smem[];
    const uint32_t sb = smem_u32(smem);

    const int t    = threadIdx.x;
    const int w    = t >> 5;
    const int lane = t & 31;
    const int wm   = w & 1;
    const int wn   = w >> 1;
    const int bm0  = blockIdx.y * 128;
    const int bn0  = blockIdx.x * 128;

    const int rA = ((lane >> 3) & 1) * 8 + (lane & 7);
    const int kA = lane >> 4;
    const int rB = ((lane >> 4) & 1) * 8 + (lane & 7);
    const int kB = (lane >> 3) & 1;

    int offA[4], xA[4];
    #pragma unroll
    for (int mt = 0; mt < 4; mt++) {
        int row = wm * 64 + mt * 16 + rA;
        offA[mt] = row * 128;
        xA[mt]   = row & 7;
    }
    int offB[2], xB[2];
    #pragma unroll
    for (int p = 0; p < 2; p++) {
        int row = wn * 32 + p * 16 + rB;
        offB[p] = row * 128;
        xB[p]   = row & 7;
    }

    const __half* Ag = A  + (size_t)bm0 * lda;
    const __half* Bg = BT + (size_t)bn0 * ldb;

    float acc[4][4][4];
    #pragma unroll
    for (int i = 0; i < 4; i++)
        #pragma unroll
        for (int j = 0; j < 4; j++)
            #pragma unroll
            for (int r = 0; r < 4; r++) acc[i][j][r] = 0.0f;

    // Prologue: stages 0 and 1 in flight (separate groups)
    load_tile(sb,                        Ag, lda, t);
    load_tile(sb + NSTAGE * TILE_BYTES,  Bg, ldb, t);
    CP_COMMIT();
    if (KT > 1) {
        load_tile(sb + TILE_BYTES,                    Ag + 64, lda, t);
        load_tile(sb + NSTAGE * TILE_BYTES + TILE_BYTES, Bg + 64, ldb, t);
        CP_COMMIT();
    }

    #pragma unroll 3
    for (int kt = 0; kt < KT; kt++) {
        if (kt == KT - 1) { CP_WAIT0(); } else { CP_WAIT1(); }
        __syncthreads();
        if (kt + 2 < KT) {
            const int s = (kt + 2) % NSTAGE;
            load_tile(sb + s * TILE_BYTES,
                      Ag + (size_t)(kt + 2) * 64, lda, t);
            load_tile(sb + NSTAGE * TILE_BYTES + s * TILE_BYTES,
                      Bg + (size_t)(kt + 2) * 64, ldb, t);
            CP_COMMIT();
        }
        const uint32_t a_base = sb + (kt % NSTAGE) * TILE_BYTES;
        const uint32_t b_base = sb + NSTAGE * TILE_BYTES + (kt % NSTAGE) * TILE_BYTES;

        #pragma unroll
        for (int ks = 0; ks < 4; ks++) {
            uint32_t af[4][4], bf[4][2];
            #pragma unroll
            for (int mt = 0; mt < 4; mt++)
                ldm_x4(af[mt], a_base + offA[mt] + (((ks * 2 + kA) ^ xA[mt]) << 4));
            #pragma unroll
            for (int p = 0; p < 2; p++) {
                uint32_t r[4];
                ldm_x4(r, b_base + offB[p] + (((ks * 2 + kB) ^ xB[p]) << 4));
                bf[2 * p][0]     = r[0];
                bf[2 * p][1]     = r[1];
                bf[2 * p + 1][0] = r[2];
                bf[2 * p + 1][1] = r[3];
            }
            #pragma unroll
            for (int mt = 0; mt < 4; mt++)
                #pragma unroll
                for (int nt = 0; nt < 4; nt++)
                    mma_f16(acc[mt][nt], af[mt], bf[nt]);
        }
        // no trailing barrier: next iter's top barrier orders buffer reuse
    }

    // Epilogue: bias (+GELU), pairwise stores
    const int g  = lane >> 2;
    const int tg = lane & 3;
    #pragma unroll
    for (int nt = 0; nt < 4; nt++) {
        const int col = bn0 + wn * 32 + nt * 8 + 2 * tg;
        const float2 bb = *(const float2*)(bias + col);
        #pragma unroll
        for (int mt = 0; mt < 4; mt++) {
            const int row = bm0 + wm * 64 + mt * 16 + g;
            #pragma unroll
            for (int h = 0; h < 2; h++) {
                float vx = acc[mt][nt][h * 2 + 0] + bb.x;
                float vy = acc[mt][nt][h * 2 + 1] + bb.y;
                if (GELU) {
                    vx = 0.5f * vx * (1.0f + erff(vx * 0.70710678118654752f));
                    vy = 0.5f * vy * (1.0f + erff(vy * 0.70710678118654752f));
                }
                OutT* dst = C + (size_t)(row + h * 8) * EMBED + col;
                if (sizeof(OutT) == 2) {
                    *(__half2*)dst = __floats2half2_rn(vx, vy);
                } else {
                    *(float2*)dst = make_float2(vx, vy);
                }
            }
        }
    }
}

// ---------------------------------------------------------------------------
extern "C" void kernel_launch(void* const* d_in, const int* in_sizes, int n_in,
                              void* d_out, int out_size)
{
    const float* frames = (const float*)d_in[0];
    const float* coords = (const float*)d_in[1];
    const int*   t_src  = (const int*)  d_in[2];
    const float* W1     = (const float*)d_in[3];
    const float* b1     = (const float*)d_in[4];
    const float* W2     = (const float*)d_in[5];
    const float* b2     = (const float*)d_in[6];
    float*       out    = (float*)d_out;

    __half *X, *H, *W1T, *W2T;
    cudaGetSymbolAddress((void**)&X,   g_X);
    cudaGetSymbolAddress((void**)&H,   g_H);
    cudaGetSymbolAddress((void**)&W1T, g_W1T);
    cudaGetSymbolAddress((void**)&W2T, g_W2T);

    cudaFuncSetAttribute(gemm_mma<4,  true,  __half>, cudaFuncAttributeMaxDynamicSharedMemorySize, S_TOTAL);
    cudaFuncSetAttribute(gemm_mma<12, false, float>,  cudaFuncAttributeMaxDynamicSharedMemorySize, S_TOTAL);

    gather_kernel<<<M_ROWS, 256>>>(frames, coords, t_src);
    {
        dim3 g1(EMBED / 32, KPAD / 32);
        transpose_h<true><<<g1, 256>>>(W1, W1T, PDIM, KPAD, EMBED);
        dim3 g2(EMBED / 32, EMBED / 32);
        transpose_h<false><<<g2, 256>>>(W2, W2T, EMBED, EMBED, EMBED);
    }

    dim3 grid(EMBED / 128, M_ROWS / 128);
    gemm_mma<4,  true,  __half><<<grid, 256, S_TOTAL>>>(X, W1T, b1, H,   KPAD,  KPAD);
    gemm_mma<12, false, float> <<<grid, 256, S_TOTAL>>>(H, W2T, b2, out, EMBED, EMBED);
}